// round 3
// baseline (speedup 1.0000x reference)
#include <cuda_runtime.h>
#include <math.h>

// Problem constants (E74DiagonalCell)
#define T_STEPS 2048
#define B_SZ    16
#define DIM_K   1024
#define N_STATE 1024
#define M_ROWS  (T_STEPS * B_SZ)          // 32768
#define STATE_N (B_SZ * N_STATE)          // 16384
#define EPSF    1e-6f

// Scratch (allocation is banned; __device__ globals are the sanctioned path)
__device__ float g_k[(size_t)M_ROWS * N_STATE];   // 134 MB
__device__ float g_v[(size_t)M_ROWS * N_STATE];   // 134 MB
__device__ float g_q[(size_t)M_ROWS * N_STATE];   // 134 MB
__device__ float g_rnorm[M_ROWS];                 // 1/(||k_row|| + eps)

// ---------------------------------------------------------------------------
// GEMM: C[m,n] = sum_d x[m,d] * W[n,d]
// x: [M_ROWS, DIM_K] row-major, W: [N_STATE, DIM_K] row-major (so this is x·Wᵀ)
// Tile 128x128x16, 256 threads, 8x8 per thread, register-prefetch pipeline.
// blockIdx.z selects which weight (k/v/q) -> x tiles reused via L2, W fits L2.
// ---------------------------------------------------------------------------
__global__ __launch_bounds__(256) void gemm3_kernel(
    const float* __restrict__ x,
    const float* __restrict__ Wk,
    const float* __restrict__ Wv,
    const float* __restrict__ Wq)
{
    __shared__ float As[16][128];   // [k][m]
    __shared__ float Bs[16][128];   // [k][n]

    const float* __restrict__ W =
        (blockIdx.z == 0) ? Wk : ((blockIdx.z == 1) ? Wv : Wq);
    float* __restrict__ C =
        (blockIdx.z == 0) ? g_k : ((blockIdx.z == 1) ? g_v : g_q);

    const int m0 = blockIdx.y * 128;
    const int n0 = blockIdx.x * 128;
    const int tid = threadIdx.x;
    const int ty = tid >> 4;          // 0..15
    const int tx = tid & 15;          // 0..15

    // Tile-load mapping: float4 index f in [0,512); row = f>>2, col4 = (f&3)*4.
    // Thread loads f = tid and f = tid + 256 (rows r0 and r0+64).
    const int r0 = tid >> 2;
    const int c0 = (tid & 3) * 4;

    const float* xA0 = x + (size_t)(m0 + r0)      * DIM_K + c0;
    const float* xA1 = x + (size_t)(m0 + r0 + 64) * DIM_K + c0;
    const float* wB0 = W + (size_t)(n0 + r0)      * DIM_K + c0;
    const float* wB1 = W + (size_t)(n0 + r0 + 64) * DIM_K + c0;

    float acc[8][8];
    #pragma unroll
    for (int i = 0; i < 8; ++i)
        #pragma unroll
        for (int j = 0; j < 8; ++j) acc[i][j] = 0.0f;

    // Prefetch tile 0
    float4 pa0 = *(const float4*)(xA0);
    float4 pa1 = *(const float4*)(xA1);
    float4 pb0 = *(const float4*)(wB0);
    float4 pb1 = *(const float4*)(wB1);

    const int NKT = DIM_K / 16;  // 64
    for (int kt = 0; kt < NKT; ++kt) {
        // Stage prefetched tile into smem (transposed: [k][row])
        As[c0 + 0][r0]      = pa0.x; As[c0 + 1][r0]      = pa0.y;
        As[c0 + 2][r0]      = pa0.z; As[c0 + 3][r0]      = pa0.w;
        As[c0 + 0][r0 + 64] = pa1.x; As[c0 + 1][r0 + 64] = pa1.y;
        As[c0 + 2][r0 + 64] = pa1.z; As[c0 + 3][r0 + 64] = pa1.w;
        Bs[c0 + 0][r0]      = pb0.x; Bs[c0 + 1][r0]      = pb0.y;
        Bs[c0 + 2][r0]      = pb0.z; Bs[c0 + 3][r0]      = pb0.w;
        Bs[c0 + 0][r0 + 64] = pb1.x; Bs[c0 + 1][r0 + 64] = pb1.y;
        Bs[c0 + 2][r0 + 64] = pb1.z; Bs[c0 + 3][r0 + 64] = pb1.w;
        __syncthreads();

        // Prefetch next tile while computing this one
        if (kt + 1 < NKT) {
            const int off = (kt + 1) * 16;
            pa0 = *(const float4*)(xA0 + off);
            pa1 = *(const float4*)(xA1 + off);
            pb0 = *(const float4*)(wB0 + off);
            pb1 = *(const float4*)(wB1 + off);
        }

        #pragma unroll
        for (int kk = 0; kk < 16; ++kk) {
            float4 a0 = *(const float4*)&As[kk][ty * 8];
            float4 a1 = *(const float4*)&As[kk][ty * 8 + 4];
            float4 b0 = *(const float4*)&Bs[kk][tx * 8];
            float4 b1 = *(const float4*)&Bs[kk][tx * 8 + 4];
            float a[8] = {a0.x, a0.y, a0.z, a0.w, a1.x, a1.y, a1.z, a1.w};
            float b[8] = {b0.x, b0.y, b0.z, b0.w, b1.x, b1.y, b1.z, b1.w};
            #pragma unroll
            for (int i = 0; i < 8; ++i)
                #pragma unroll
                for (int j = 0; j < 8; ++j)
                    acc[i][j] = fmaf(a[i], b[j], acc[i][j]);
        }
        __syncthreads();
    }

    // Epilogue: vectorized stores
    #pragma unroll
    for (int i = 0; i < 8; ++i) {
        const size_t m = (size_t)(m0 + ty * 8 + i);
        float4 o0 = make_float4(acc[i][0], acc[i][1], acc[i][2], acc[i][3]);
        float4 o1 = make_float4(acc[i][4], acc[i][5], acc[i][6], acc[i][7]);
        *(float4*)(C + m * N_STATE + n0 + tx * 8)     = o0;
        *(float4*)(C + m * N_STATE + n0 + tx * 8 + 4) = o1;
    }
}

// ---------------------------------------------------------------------------
// Row norms of k: one warp per row; stores 1/(||k||+eps).
// ---------------------------------------------------------------------------
__global__ __launch_bounds__(256) void rnorm_kernel()
{
    const int warp = threadIdx.x >> 5;
    const int lane = threadIdx.x & 31;
    const int row = blockIdx.x * 8 + warp;   // 4096 blocks * 8 warps = 32768 rows

    const float4* kp = (const float4*)(g_k + (size_t)row * N_STATE);
    float ss = 0.0f;
    #pragma unroll
    for (int j = 0; j < 8; ++j) {            // 8 * 32 lanes * 4 = 1024 elems
        float4 v = kp[lane + j * 32];
        ss = fmaf(v.x, v.x, ss);
        ss = fmaf(v.y, v.y, ss);
        ss = fmaf(v.z, v.z, ss);
        ss = fmaf(v.w, v.w, ss);
    }
    #pragma unroll
    for (int o = 16; o > 0; o >>= 1)
        ss += __shfl_xor_sync(0xFFFFFFFFu, ss, o);

    if (lane == 0)
        g_rnorm[row] = 1.0f / (sqrtf(ss) + EPSF);
}

// ---------------------------------------------------------------------------
// Sequential scan: one thread per (b, n) state.
//   S = tanh(S*(1 - kn^2) + v*kn);  Sq = S*q;  out = Sq^2 * sigmoid(Sq)
// ---------------------------------------------------------------------------
__global__ __launch_bounds__(256) void scan_kernel(float* __restrict__ out,
                                                   float* __restrict__ s_final)
{
    const int s = blockIdx.x * 256 + threadIdx.x;    // 0..16383
    const int b = s >> 10;                           // state row -> batch

    float S = 0.0f;

    #pragma unroll 4
    for (int t = 0; t < T_STEPS; ++t) {
        const int idx = t * STATE_N + s;
        const float kraw = g_k[idx];
        const float v    = g_v[idx];
        const float q    = g_q[idx];
        const float rn   = g_rnorm[t * B_SZ + b];

        const float kn = kraw * rn;
        S = tanhf(fmaf(S, 1.0f - kn * kn, v * kn));
        const float Sq = S * q;
        // Sq * silu(Sq) = Sq^2 * sigmoid(Sq)
        out[idx] = (Sq * Sq) / (1.0f + expf(-Sq));
    }

    if (s_final)
        s_final[s] = S;
}

// ---------------------------------------------------------------------------
// Launch
// ---------------------------------------------------------------------------
extern "C" void kernel_launch(void* const* d_in, const int* in_sizes, int n_in,
                              void* d_out, int out_size)
{
    const float* x  = (const float*)d_in[0];
    const float* Wk = (const float*)d_in[1];
    const float* Wv = (const float*)d_in[2];
    const float* Wq = (const float*)d_in[3];
    float* out = (float*)d_out;

    // Projections k, v, q  (N/128=8, M/128=256, 3 weights)
    dim3 ggrid(N_STATE / 128, M_ROWS / 128, 3);
    gemm3_kernel<<<ggrid, 256>>>(x, Wk, Wv, Wq);

    // Reciprocal row norms of k
    rnorm_kernel<<<M_ROWS / 8, 256>>>();

    // Scan over time; output layout: [T,B,N] then S_final [B,N] if present
    float* s_final = nullptr;
    if (out_size >= M_ROWS * N_STATE + STATE_N)
        s_final = out + (size_t)M_ROWS * N_STATE;
    scan_kernel<<<STATE_N / 256, 256>>>(out, s_final);
}

// round 5
// speedup vs baseline: 1.6251x; 1.6251x over previous
#include <cuda_runtime.h>
#include <cuda_bf16.h>
#include <math.h>
#include <stdint.h>

// Problem constants (E74DiagonalCell)
#define T_STEPS 2048
#define B_SZ    16
#define DIM_K   1024
#define N_STATE 1024
#define M_ROWS  (T_STEPS * B_SZ)          // 32768
#define STATE_N (B_SZ * N_STATE)          // 16384
#define EPSF    1e-6f

// GEMM tiling (sm80-style mma.sync path; tcgen05 unavailable at compute_100)
#define BM 128
#define BN 128
#define BK 32
#define NKT (DIM_K / BK)                   // 32
#define LDS_B 80                           // padded row stride in bytes (32 bf16 + 8 pad)
#define TILE_BYTES (BM * LDS_B)            // 10240
#define OFF_AH 0
#define OFF_AL (1 * TILE_BYTES)
#define OFF_BH (2 * TILE_BYTES)
#define OFF_BL (3 * TILE_BYTES)
#define STAGE_BYTES (4 * TILE_BYTES)       // 40960
#define N_STAGE 3
#define SMEM_TOTAL (N_STAGE * STAGE_BYTES) // 122880

// ---------------------------------------------------------------------------
// Scratch (allocation banned -> __device__ globals)
// ---------------------------------------------------------------------------
__device__ float g_k[(size_t)M_ROWS * N_STATE];
__device__ float g_v[(size_t)M_ROWS * N_STATE];
__device__ float g_q[(size_t)M_ROWS * N_STATE];
__device__ float g_rnorm[M_ROWS];

__device__ __align__(16) __nv_bfloat16 g_xh[(size_t)M_ROWS * DIM_K];
__device__ __align__(16) __nv_bfloat16 g_xl[(size_t)M_ROWS * DIM_K];
__device__ __align__(16) __nv_bfloat16 g_wh[(size_t)3 * N_STATE * DIM_K];
__device__ __align__(16) __nv_bfloat16 g_wl[(size_t)3 * N_STATE * DIM_K];

// ---------------------------------------------------------------------------
// PTX helpers (all compute_80-level; nothing arch-'a'-gated)
// ---------------------------------------------------------------------------
__device__ __forceinline__ uint32_t smem_u32(const void* p) {
    uint32_t a;
    asm("{ .reg .u64 t; cvta.to.shared.u64 t, %1; cvt.u32.u64 %0, t; }"
        : "=r"(a) : "l"(p));
    return a;
}

__device__ __forceinline__ void cp_async16(uint32_t dst, const void* src) {
    asm volatile("cp.async.cg.shared.global [%0], [%1], 16;" :: "r"(dst), "l"(src));
}

__device__ __forceinline__ void ldsm4(uint32_t* r, uint32_t addr) {
    asm volatile("ldmatrix.sync.aligned.m8n8.x4.shared.b16 {%0,%1,%2,%3}, [%4];"
                 : "=r"(r[0]), "=r"(r[1]), "=r"(r[2]), "=r"(r[3]) : "r"(addr));
}

__device__ __forceinline__ void mma_bf16(float* c, const uint32_t* a,
                                         uint32_t b0, uint32_t b1) {
    asm volatile(
        "mma.sync.aligned.m16n8k16.row.col.f32.bf16.bf16.f32 "
        "{%0,%1,%2,%3}, {%4,%5,%6,%7}, {%8,%9}, {%0,%1,%2,%3};"
        : "+f"(c[0]), "+f"(c[1]), "+f"(c[2]), "+f"(c[3])
        : "r"(a[0]), "r"(a[1]), "r"(a[2]), "r"(a[3]), "r"(b0), "r"(b1));
}

// ---------------------------------------------------------------------------
// fp32 -> bf16 hi/lo split.  which: 0 -> x, 1..3 -> W_{k,v,q}
// ---------------------------------------------------------------------------
__global__ __launch_bounds__(256) void split_kernel(const float* __restrict__ src,
                                                    int which, int n4) {
    __nv_bfloat16 *h, *l;
    if (which == 0) { h = g_xh; l = g_xl; }
    else {
        const size_t off = (size_t)(which - 1) * N_STATE * DIM_K;
        h = g_wh + off; l = g_wl + off;
    }
    const int i = blockIdx.x * 256 + threadIdx.x;
    if (i >= n4) return;
    const float4 v = ((const float4*)src)[i];
    const __nv_bfloat16 h0 = __float2bfloat16(v.x);
    const __nv_bfloat16 h1 = __float2bfloat16(v.y);
    const __nv_bfloat16 h2 = __float2bfloat16(v.z);
    const __nv_bfloat16 h3 = __float2bfloat16(v.w);
    const __nv_bfloat16 l0 = __float2bfloat16(v.x - __bfloat162float(h0));
    const __nv_bfloat16 l1 = __float2bfloat16(v.y - __bfloat162float(h1));
    const __nv_bfloat16 l2 = __float2bfloat16(v.z - __bfloat162float(h2));
    const __nv_bfloat16 l3 = __float2bfloat16(v.w - __bfloat162float(h3));
    __nv_bfloat162* hp = (__nv_bfloat162*)h;
    __nv_bfloat162* lp = (__nv_bfloat162*)l;
    hp[2 * i]     = __halves2bfloat162(h0, h1);
    hp[2 * i + 1] = __halves2bfloat162(h2, h3);
    lp[2 * i]     = __halves2bfloat162(l0, l1);
    lp[2 * i + 1] = __halves2bfloat162(l2, l3);
}

// ---------------------------------------------------------------------------
// cp.async one BK=32 chunk of all four tiles into a stage.
// Each thread: row = tid/2, chunk pair c = (tid&1)*2 -> 8 cp.async of 16B.
// ---------------------------------------------------------------------------
__device__ __forceinline__ void issue_loads(
    uint32_t stage, int kt, int m0, int n0, int tid,
    const __nv_bfloat16* __restrict__ wh, const __nv_bfloat16* __restrict__ wl)
{
    const int kc = kt * BK;
    const int r = tid >> 1;
    const int c = (tid & 1) * 2;               // 16B chunk index (0 or 2)
    const size_t ga = (size_t)(m0 + r) * DIM_K + kc + c * 8;
    const size_t gb = (size_t)(n0 + r) * DIM_K + kc + c * 8;
    const uint32_t so = (uint32_t)(r * LDS_B + c * 16);

    cp_async16(stage + OFF_AH + so,      g_xh + ga);
    cp_async16(stage + OFF_AH + so + 16, g_xh + ga + 8);
    cp_async16(stage + OFF_AL + so,      g_xl + ga);
    cp_async16(stage + OFF_AL + so + 16, g_xl + ga + 8);
    cp_async16(stage + OFF_BH + so,      wh + gb);
    cp_async16(stage + OFF_BH + so + 16, wh + gb + 8);
    cp_async16(stage + OFF_BL + so,      wl + gb);
    cp_async16(stage + OFF_BL + so + 16, wl + gb + 8);
}

// ---------------------------------------------------------------------------
// GEMM: C[m,n] = sum_d x[m,d] * W[n,d], 3-term bf16 split via mma.sync.
// grid = (N/BN=8, M/BM=256, 3); 256 threads; warp tile 64x32.
// ---------------------------------------------------------------------------
__global__ __launch_bounds__(256, 1) void gemm_mma_kernel()
{
    extern __shared__ __align__(16) char smem[];
    const int tid  = threadIdx.x;
    const int lane = tid & 31;
    const int wid  = tid >> 5;
    const int n0 = blockIdx.x * BN;
    const int m0 = blockIdx.y * BM;
    const int z  = blockIdx.z;

    const size_t woff = (size_t)z * N_STATE * DIM_K;
    const __nv_bfloat16* wh = g_wh + woff;
    const __nv_bfloat16* wl = g_wl + woff;
    float* C = (z == 0) ? g_k : ((z == 1) ? g_v : g_q);

    const uint32_t sb = smem_u32(smem);

    // Warp tile origin within the CTA tile
    const int wm = (wid & 1) * 64;
    const int wn = (wid >> 1) * 32;

    // ldmatrix lane addressing: 16 rows x (two 8-col halves)
    const int lrow = (lane & 7) + (((lane >> 3) & 1) << 3);  // 0..15
    const int lkB  = (lane >> 4) * 16;                       // byte offset 0 or 16

    float acc[4][4][4];
    #pragma unroll
    for (int i = 0; i < 4; ++i)
        #pragma unroll
        for (int j = 0; j < 4; ++j)
            #pragma unroll
            for (int e = 0; e < 4; ++e) acc[i][j][e] = 0.0f;

    // Prologue: stages 0 and 1
    issue_loads(sb, 0, m0, n0, tid, wh, wl);
    asm volatile("cp.async.commit_group;" ::: "memory");
    issue_loads(sb + STAGE_BYTES, 1, m0, n0, tid, wh, wl);
    asm volatile("cp.async.commit_group;" ::: "memory");

    for (int kt = 0; kt < NKT; ++kt) {
        if (kt < NKT - 1) asm volatile("cp.async.wait_group 1;" ::: "memory");
        else              asm volatile("cp.async.wait_group 0;" ::: "memory");
        __syncthreads();

        // Refill the stage consumed at iteration kt-1 with chunk kt+2
        if (kt + 2 < NKT) {
            const uint32_t st = sb + (uint32_t)((kt + 2) % N_STAGE) * STAGE_BYTES;
            issue_loads(st, kt + 2, m0, n0, tid, wh, wl);
            asm volatile("cp.async.commit_group;" ::: "memory");
        }

        const uint32_t stage = sb + (uint32_t)(kt % N_STAGE) * STAGE_BYTES;

        #pragma unroll
        for (int kk = 0; kk < 2; ++kk) {       // two k16 halves of BK=32
            const uint32_t kb = (uint32_t)(kk * 32 + lkB);  // byte offset in row

            uint32_t ah[4][4], al[4][4];
            #pragma unroll
            for (int mi = 0; mi < 4; ++mi) {
                const uint32_t ra = (uint32_t)((wm + mi * 16 + lrow) * LDS_B) + kb;
                ldsm4(ah[mi], stage + OFF_AH + ra);
                ldsm4(al[mi], stage + OFF_AL + ra);
            }
            uint32_t bh[2][4], bl[2][4];
            #pragma unroll
            for (int nj = 0; nj < 2; ++nj) {
                const uint32_t rb = (uint32_t)((wn + nj * 16 + lrow) * LDS_B) + kb;
                ldsm4(bh[nj], stage + OFF_BH + rb);
                ldsm4(bl[nj], stage + OFF_BL + rb);
            }

            #pragma unroll
            for (int mi = 0; mi < 4; ++mi) {
                #pragma unroll
                for (int ni = 0; ni < 4; ++ni) {
                    const int nj = ni >> 1, p = ni & 1;
                    // n-tile even: regs {r0, r2}; odd: {r1, r3}
                    const uint32_t bh0 = bh[nj][p],     bh1 = bh[nj][p + 2];
                    const uint32_t bl0 = bl[nj][p],     bl1 = bl[nj][p + 2];
                    mma_bf16(acc[mi][ni], ah[mi], bh0, bh1);   // hi*hi
                    mma_bf16(acc[mi][ni], ah[mi], bl0, bl1);   // hi*lo
                    mma_bf16(acc[mi][ni], al[mi], bh0, bh1);   // lo*hi
                }
            }
        }
        __syncthreads();
    }

    // Epilogue: acc[mi][ni] fragment: rows lane/4 and lane/4+8, cols (lane%4)*2
    const int er = lane >> 2;
    const int ec = (lane & 3) * 2;
    #pragma unroll
    for (int mi = 0; mi < 4; ++mi) {
        #pragma unroll
        for (int ni = 0; ni < 4; ++ni) {
            const size_t row = (size_t)(m0 + wm + mi * 16 + er);
            const size_t col = (size_t)(n0 + wn + ni * 8 + ec);
            *(float2*)(C + row * N_STATE + col) =
                make_float2(acc[mi][ni][0], acc[mi][ni][1]);
            *(float2*)(C + (row + 8) * N_STATE + col) =
                make_float2(acc[mi][ni][2], acc[mi][ni][3]);
        }
    }
}

// ---------------------------------------------------------------------------
// Row norms of k: one warp per row; stores 1/(||k||+eps).
// ---------------------------------------------------------------------------
__global__ __launch_bounds__(256) void rnorm_kernel()
{
    const int warp = threadIdx.x >> 5;
    const int lane = threadIdx.x & 31;
    const int row = blockIdx.x * 8 + warp;

    const float4* kp = (const float4*)(g_k + (size_t)row * N_STATE);
    float ss = 0.0f;
    #pragma unroll
    for (int j = 0; j < 8; ++j) {
        float4 v = kp[lane + j * 32];
        ss = fmaf(v.x, v.x, ss);
        ss = fmaf(v.y, v.y, ss);
        ss = fmaf(v.z, v.z, ss);
        ss = fmaf(v.w, v.w, ss);
    }
    #pragma unroll
    for (int o = 16; o > 0; o >>= 1)
        ss += __shfl_xor_sync(0xFFFFFFFFu, ss, o);

    if (lane == 0)
        g_rnorm[row] = 1.0f / (sqrtf(ss) + EPSF);
}

// ---------------------------------------------------------------------------
// Sequential scan: one thread per (b, n). rnorm cached in smem (one b per CTA).
// 128 threads x 128 CTAs spreads across more SMs than 256x64.
// ---------------------------------------------------------------------------
__global__ __launch_bounds__(128) void scan_kernel(float* __restrict__ out,
                                                   float* __restrict__ s_final)
{
    __shared__ float srn[T_STEPS];
    const int s = blockIdx.x * 128 + threadIdx.x;    // 0..16383
    const int b = s >> 10;                           // whole CTA shares one b

    for (int t = threadIdx.x; t < T_STEPS; t += 128)
        srn[t] = g_rnorm[t * B_SZ + b];
    __syncthreads();

    float S = 0.0f;

    #pragma unroll 8
    for (int t = 0; t < T_STEPS; ++t) {
        const int idx = t * STATE_N + s;
        const float kraw = __ldcs(g_k + idx);
        const float v    = __ldcs(g_v + idx);
        const float q    = __ldcs(g_q + idx);
        const float rn   = srn[t];

        const float kn = kraw * rn;
        S = tanhf(fmaf(S, 1.0f - kn * kn, v * kn));
        const float Sq = S * q;
        const float o = (Sq * Sq) / (1.0f + __expf(-Sq));
        __stcs(out + idx, o);
    }

    if (s_final)
        s_final[s] = S;
}

// ---------------------------------------------------------------------------
// Launch
// ---------------------------------------------------------------------------
extern "C" void kernel_launch(void* const* d_in, const int* in_sizes, int n_in,
                              void* d_out, int out_size)
{
    const float* x  = (const float*)d_in[0];
    const float* Wk = (const float*)d_in[1];
    const float* Wv = (const float*)d_in[2];
    const float* Wq = (const float*)d_in[3];
    float* out = (float*)d_out;

    // bf16 hi/lo splits
    const int n4x = (M_ROWS * DIM_K) / 4;
    const int n4w = (N_STATE * DIM_K) / 4;
    split_kernel<<<(n4x + 255) / 256, 256>>>(x,  0, n4x);
    split_kernel<<<(n4w + 255) / 256, 256>>>(Wk, 1, n4w);
    split_kernel<<<(n4w + 255) / 256, 256>>>(Wv, 2, n4w);
    split_kernel<<<(n4w + 255) / 256, 256>>>(Wq, 3, n4w);

    // Tensor-core GEMM for k, v, q
    cudaFuncSetAttribute(gemm_mma_kernel,
                         cudaFuncAttributeMaxDynamicSharedMemorySize, SMEM_TOTAL);
    dim3 ggrid(N_STATE / BN, M_ROWS / BM, 3);
    gemm_mma_kernel<<<ggrid, 256, SMEM_TOTAL>>>();

    // Reciprocal row norms of k
    rnorm_kernel<<<M_ROWS / 8, 256>>>();

    // Scan over time
    float* s_final = nullptr;
    if (out_size >= M_ROWS * N_STATE + STATE_N)
        s_final = out + (size_t)M_ROWS * N_STATE;
    scan_kernel<<<STATE_N / 128, 128>>>(out, s_final);
}

// round 6
// speedup vs baseline: 1.6332x; 1.0050x over previous
#include <cuda_runtime.h>
#include <cuda_bf16.h>
#include <math.h>
#include <stdint.h>

// Problem constants (E74DiagonalCell)
#define T_STEPS 2048
#define B_SZ    16
#define DIM_K   1024
#define N_STATE 1024
#define M_ROWS  (T_STEPS * B_SZ)          // 32768
#define STATE_N (B_SZ * N_STATE)          // 16384
#define EPSF    1e-6f

// GEMM tiling (sm80-style mma.sync path; tcgen05 unavailable at compute_100)
#define BM 128
#define BN 128
#define BK 32
#define NKT (DIM_K / BK)                   // 32
#define LDS_B 80                           // padded row stride in bytes (32 bf16 + 8 pad)
#define TILE_BYTES (BM * LDS_B)            // 10240
#define OFF_AH 0
#define OFF_AL (1 * TILE_BYTES)
#define OFF_BH (2 * TILE_BYTES)
#define OFF_BL (3 * TILE_BYTES)
#define STAGE_BYTES (4 * TILE_BYTES)       // 40960
#define N_STAGE 3
#define SMEM_TOTAL (N_STAGE * STAGE_BYTES) // 122880

// ---------------------------------------------------------------------------
// Scratch (allocation banned -> __device__ globals)
// ---------------------------------------------------------------------------
__device__ float g_k[(size_t)M_ROWS * N_STATE];
__device__ float g_v[(size_t)M_ROWS * N_STATE];
__device__ float g_q[(size_t)M_ROWS * N_STATE];
__device__ float g_rnorm[M_ROWS];

__device__ __align__(16) __nv_bfloat16 g_xh[(size_t)M_ROWS * DIM_K];
__device__ __align__(16) __nv_bfloat16 g_xl[(size_t)M_ROWS * DIM_K];
__device__ __align__(16) __nv_bfloat16 g_wh[(size_t)3 * N_STATE * DIM_K];
__device__ __align__(16) __nv_bfloat16 g_wl[(size_t)3 * N_STATE * DIM_K];

// ---------------------------------------------------------------------------
// PTX helpers (all compute_80-level; nothing arch-'a'-gated)
// ---------------------------------------------------------------------------
__device__ __forceinline__ uint32_t smem_u32(const void* p) {
    uint32_t a;
    asm("{ .reg .u64 t; cvta.to.shared.u64 t, %1; cvt.u32.u64 %0, t; }"
        : "=r"(a) : "l"(p));
    return a;
}

__device__ __forceinline__ void cp_async16(uint32_t dst, const void* src) {
    asm volatile("cp.async.cg.shared.global [%0], [%1], 16;" :: "r"(dst), "l"(src));
}

__device__ __forceinline__ void ldsm4(uint32_t* r, uint32_t addr) {
    asm volatile("ldmatrix.sync.aligned.m8n8.x4.shared.b16 {%0,%1,%2,%3}, [%4];"
                 : "=r"(r[0]), "=r"(r[1]), "=r"(r[2]), "=r"(r[3]) : "r"(addr));
}

__device__ __forceinline__ void mma_bf16(float* c, const uint32_t* a,
                                         uint32_t b0, uint32_t b1) {
    asm volatile(
        "mma.sync.aligned.m16n8k16.row.col.f32.bf16.bf16.f32 "
        "{%0,%1,%2,%3}, {%4,%5,%6,%7}, {%8,%9}, {%0,%1,%2,%3};"
        : "+f"(c[0]), "+f"(c[1]), "+f"(c[2]), "+f"(c[3])
        : "r"(a[0]), "r"(a[1]), "r"(a[2]), "r"(a[3]), "r"(b0), "r"(b1));
}

// ---------------------------------------------------------------------------
// fp32 -> bf16 hi/lo split, ALL tensors in one launch.
// Linear float4 index space: [0, n4x) -> x ; then 3 weight blocks of n4w each.
// ---------------------------------------------------------------------------
__global__ __launch_bounds__(256) void split_all_kernel(
    const float* __restrict__ x,  const float* __restrict__ Wk,
    const float* __restrict__ Wv, const float* __restrict__ Wq)
{
    const int n4x = (M_ROWS * DIM_K) / 4;
    const int n4w = (N_STATE * DIM_K) / 4;
    const int i = blockIdx.x * 256 + threadIdx.x;

    const float* src;
    __nv_bfloat16 *h, *l;
    int j;
    if (i < n4x) {
        src = x; h = g_xh; l = g_xl; j = i;
    } else {
        const int w = (i - n4x) / n4w;           // 0..2
        j = (i - n4x) - w * n4w;
        src = (w == 0) ? Wk : ((w == 1) ? Wv : Wq);
        const size_t off = (size_t)w * N_STATE * DIM_K;
        h = g_wh + off; l = g_wl + off;
    }

    const float4 v = ((const float4*)src)[j];
    const __nv_bfloat16 h0 = __float2bfloat16(v.x);
    const __nv_bfloat16 h1 = __float2bfloat16(v.y);
    const __nv_bfloat16 h2 = __float2bfloat16(v.z);
    const __nv_bfloat16 h3 = __float2bfloat16(v.w);
    const __nv_bfloat16 l0 = __float2bfloat16(v.x - __bfloat162float(h0));
    const __nv_bfloat16 l1 = __float2bfloat16(v.y - __bfloat162float(h1));
    const __nv_bfloat16 l2 = __float2bfloat16(v.z - __bfloat162float(h2));
    const __nv_bfloat16 l3 = __float2bfloat16(v.w - __bfloat162float(h3));
    __nv_bfloat162* hp = (__nv_bfloat162*)h;
    __nv_bfloat162* lp = (__nv_bfloat162*)l;
    hp[2 * j]     = __halves2bfloat162(h0, h1);
    hp[2 * j + 1] = __halves2bfloat162(h2, h3);
    lp[2 * j]     = __halves2bfloat162(l0, l1);
    lp[2 * j + 1] = __halves2bfloat162(l2, l3);
}

// ---------------------------------------------------------------------------
// cp.async one BK=32 chunk of all four tiles into a stage.
// ---------------------------------------------------------------------------
__device__ __forceinline__ void issue_loads(
    uint32_t stage, int kt, int m0, int n0, int tid,
    const __nv_bfloat16* __restrict__ wh, const __nv_bfloat16* __restrict__ wl)
{
    const int kc = kt * BK;
    const int r = tid >> 1;
    const int c = (tid & 1) * 2;               // 16B chunk index (0 or 2)
    const size_t ga = (size_t)(m0 + r) * DIM_K + kc + c * 8;
    const size_t gb = (size_t)(n0 + r) * DIM_K + kc + c * 8;
    const uint32_t so = (uint32_t)(r * LDS_B + c * 16);

    cp_async16(stage + OFF_AH + so,      g_xh + ga);
    cp_async16(stage + OFF_AH + so + 16, g_xh + ga + 8);
    cp_async16(stage + OFF_AL + so,      g_xl + ga);
    cp_async16(stage + OFF_AL + so + 16, g_xl + ga + 8);
    cp_async16(stage + OFF_BH + so,      wh + gb);
    cp_async16(stage + OFF_BH + so + 16, wh + gb + 8);
    cp_async16(stage + OFF_BL + so,      wl + gb);
    cp_async16(stage + OFF_BL + so + 16, wl + gb + 8);
}

// ---------------------------------------------------------------------------
// GEMM: C[m,n] = sum_d x[m,d] * W[n,d], 3-term bf16 split via mma.sync.
// grid = (N/BN=8, M/BM=256, 3); 256 threads; warp tile 64x32.
// MMA stream is TERM-MAJOR: 16 independent accumulators between reuses.
// ---------------------------------------------------------------------------
__global__ __launch_bounds__(256, 1) void gemm_mma_kernel()
{
    extern __shared__ __align__(16) char smem[];
    const int tid  = threadIdx.x;
    const int lane = tid & 31;
    const int wid  = tid >> 5;
    const int n0 = blockIdx.x * BN;
    const int m0 = blockIdx.y * BM;
    const int z  = blockIdx.z;

    const size_t woff = (size_t)z * N_STATE * DIM_K;
    const __nv_bfloat16* wh = g_wh + woff;
    const __nv_bfloat16* wl = g_wl + woff;
    float* C = (z == 0) ? g_k : ((z == 1) ? g_v : g_q);

    const uint32_t sb = smem_u32(smem);

    // Warp tile origin within the CTA tile
    const int wm = (wid & 1) * 64;
    const int wn = (wid >> 1) * 32;

    // ldmatrix lane addressing: 16 rows x (two 8-col halves)
    const int lrow = (lane & 7) + (((lane >> 3) & 1) << 3);  // 0..15
    const int lkB  = (lane >> 4) * 16;                       // byte offset 0 or 16

    float acc[4][4][4];
    #pragma unroll
    for (int i = 0; i < 4; ++i)
        #pragma unroll
        for (int j = 0; j < 4; ++j)
            #pragma unroll
            for (int e = 0; e < 4; ++e) acc[i][j][e] = 0.0f;

    // Prologue: stages 0 and 1
    issue_loads(sb, 0, m0, n0, tid, wh, wl);
    asm volatile("cp.async.commit_group;" ::: "memory");
    issue_loads(sb + STAGE_BYTES, 1, m0, n0, tid, wh, wl);
    asm volatile("cp.async.commit_group;" ::: "memory");

    for (int kt = 0; kt < NKT; ++kt) {
        if (kt < NKT - 1) asm volatile("cp.async.wait_group 1;" ::: "memory");
        else              asm volatile("cp.async.wait_group 0;" ::: "memory");
        __syncthreads();

        // Refill the stage consumed at iteration kt-1 with chunk kt+2
        if (kt + 2 < NKT) {
            const uint32_t st = sb + (uint32_t)((kt + 2) % N_STAGE) * STAGE_BYTES;
            issue_loads(st, kt + 2, m0, n0, tid, wh, wl);
            asm volatile("cp.async.commit_group;" ::: "memory");
        }

        const uint32_t stage = sb + (uint32_t)(kt % N_STAGE) * STAGE_BYTES;

        #pragma unroll
        for (int kk = 0; kk < 2; ++kk) {       // two k16 halves of BK=32
            const uint32_t kb = (uint32_t)(kk * 32 + lkB);  // byte offset in row

            uint32_t ah[4][4], al[4][4];
            #pragma unroll
            for (int mi = 0; mi < 4; ++mi) {
                const uint32_t ra = (uint32_t)((wm + mi * 16 + lrow) * LDS_B) + kb;
                ldsm4(ah[mi], stage + OFF_AH + ra);
                ldsm4(al[mi], stage + OFF_AL + ra);
            }
            uint32_t bh[2][4], bl[2][4];
            #pragma unroll
            for (int nj = 0; nj < 2; ++nj) {
                const uint32_t rb = (uint32_t)((wn + nj * 16 + lrow) * LDS_B) + kb;
                ldsm4(bh[nj], stage + OFF_BH + rb);
                ldsm4(bl[nj], stage + OFF_BL + rb);
            }

            // TERM-MAJOR: all hi*hi, then all hi*lo, then all lo*hi.
            // Each accumulator is touched once per 16-MMA sweep -> no RAW chains.
            #pragma unroll
            for (int mi = 0; mi < 4; ++mi)
                #pragma unroll
                for (int ni = 0; ni < 4; ++ni) {
                    const int nj = ni >> 1, p = ni & 1;
                    mma_bf16(acc[mi][ni], ah[mi], bh[nj][p], bh[nj][p + 2]);
                }
            #pragma unroll
            for (int mi = 0; mi < 4; ++mi)
                #pragma unroll
                for (int ni = 0; ni < 4; ++ni) {
                    const int nj = ni >> 1, p = ni & 1;
                    mma_bf16(acc[mi][ni], ah[mi], bl[nj][p], bl[nj][p + 2]);
                }
            #pragma unroll
            for (int mi = 0; mi < 4; ++mi)
                #pragma unroll
                for (int ni = 0; ni < 4; ++ni) {
                    const int nj = ni >> 1, p = ni & 1;
                    mma_bf16(acc[mi][ni], al[mi], bh[nj][p], bh[nj][p + 2]);
                }
        }
        __syncthreads();
    }

    // Epilogue: acc[mi][ni] fragment: rows lane/4 and lane/4+8, cols (lane%4)*2
    const int er = lane >> 2;
    const int ec = (lane & 3) * 2;
    #pragma unroll
    for (int mi = 0; mi < 4; ++mi) {
        #pragma unroll
        for (int ni = 0; ni < 4; ++ni) {
            const size_t row = (size_t)(m0 + wm + mi * 16 + er);
            const size_t col = (size_t)(n0 + wn + ni * 8 + ec);
            *(float2*)(C + row * N_STATE + col) =
                make_float2(acc[mi][ni][0], acc[mi][ni][1]);
            *(float2*)(C + (row + 8) * N_STATE + col) =
                make_float2(acc[mi][ni][2], acc[mi][ni][3]);
        }
    }
}

// ---------------------------------------------------------------------------
// Row norms of k: one warp per row; stores 1/(||k||+eps).
// ---------------------------------------------------------------------------
__global__ __launch_bounds__(256) void rnorm_kernel()
{
    const int warp = threadIdx.x >> 5;
    const int lane = threadIdx.x & 31;
    const int row = blockIdx.x * 8 + warp;

    const float4* kp = (const float4*)(g_k + (size_t)row * N_STATE);
    float ss = 0.0f;
    #pragma unroll
    for (int j = 0; j < 8; ++j) {
        float4 v = kp[lane + j * 32];
        ss = fmaf(v.x, v.x, ss);
        ss = fmaf(v.y, v.y, ss);
        ss = fmaf(v.z, v.z, ss);
        ss = fmaf(v.w, v.w, ss);
    }
    #pragma unroll
    for (int o = 16; o > 0; o >>= 1)
        ss += __shfl_xor_sync(0xFFFFFFFFu, ss, o);

    if (lane == 0)
        g_rnorm[row] = 1.0f / (sqrtf(ss) + EPSF);
}

// ---------------------------------------------------------------------------
// Sequential scan: one thread per (b, n). rnorm cached in smem (one b per CTA).
// ---------------------------------------------------------------------------
__global__ __launch_bounds__(128) void scan_kernel(float* __restrict__ out,
                                                   float* __restrict__ s_final)
{
    __shared__ float srn[T_STEPS];
    const int s = blockIdx.x * 128 + threadIdx.x;    // 0..16383
    const int b = s >> 10;                           // whole CTA shares one b

    for (int t = threadIdx.x; t < T_STEPS; t += 128)
        srn[t] = g_rnorm[t * B_SZ + b];
    __syncthreads();

    float S = 0.0f;

    #pragma unroll 8
    for (int t = 0; t < T_STEPS; ++t) {
        const int idx = t * STATE_N + s;
        const float kraw = __ldcs(g_k + idx);
        const float v    = __ldcs(g_v + idx);
        const float q    = __ldcs(g_q + idx);
        const float rn   = srn[t];

        const float kn = kraw * rn;
        S = tanhf(fmaf(S, 1.0f - kn * kn, v * kn));
        const float Sq = S * q;
        const float o = (Sq * Sq) / (1.0f + __expf(-Sq));
        __stcs(out + idx, o);
    }

    if (s_final)
        s_final[s] = S;
}

// ---------------------------------------------------------------------------
// Launch
// ---------------------------------------------------------------------------
extern "C" void kernel_launch(void* const* d_in, const int* in_sizes, int n_in,
                              void* d_out, int out_size)
{
    const float* x  = (const float*)d_in[0];
    const float* Wk = (const float*)d_in[1];
    const float* Wv = (const float*)d_in[2];
    const float* Wq = (const float*)d_in[3];
    float* out = (float*)d_out;

    // bf16 hi/lo splits (single launch; also steers ncu -s 5 onto the GEMM)
    const int n4tot = (M_ROWS * DIM_K) / 4 + 3 * ((N_STATE * DIM_K) / 4);
    split_all_kernel<<<(n4tot + 255) / 256, 256>>>(x, Wk, Wv, Wq);

    // Tensor-core GEMM for k, v, q
    cudaFuncSetAttribute(gemm_mma_kernel,
                         cudaFuncAttributeMaxDynamicSharedMemorySize, SMEM_TOTAL);
    dim3 ggrid(N_STATE / BN, M_ROWS / BM, 3);
    gemm_mma_kernel<<<ggrid, 256, SMEM_TOTAL>>>();

    // Reciprocal row norms of k
    rnorm_kernel<<<M_ROWS / 8, 256>>>();

    // Scan over time
    float* s_final = nullptr;
    if (out_size >= M_ROWS * N_STATE + STATE_N)
        s_final = out + (size_t)M_ROWS * N_STATE;
    scan_kernel<<<STATE_N / 128, 128>>>(out, s_final);
}

// round 7
// speedup vs baseline: 2.7969x; 1.7126x over previous
#include <cuda_runtime.h>
#include <cuda_fp16.h>
#include <math.h>
#include <stdint.h>

// Problem constants (E74DiagonalCell)
#define T_STEPS 2048
#define B_SZ    16
#define DIM_K   1024
#define N_STATE 1024
#define M_ROWS  (T_STEPS * B_SZ)          // 32768
#define STATE_N (B_SZ * N_STATE)          // 16384
#define EPSF    1e-6f

// GEMM tiling (fp16 single-pass mma.sync; tcgen05 unavailable at compute_100)
#define BM 128
#define BN 128
#define BK 32
#define NKT (DIM_K / BK)                   // 32
#define LDS_B 80                           // padded row stride bytes (64B data + 16 pad)
#define TILE_BYTES (BM * LDS_B)            // 10240
#define OFF_A 0
#define OFF_B TILE_BYTES
#define STAGE_BYTES (2 * TILE_BYTES)       // 20480
#define N_STAGE 4
#define SMEM_TOTAL (N_STAGE * STAGE_BYTES) // 81920 -> 2 CTAs/SM

// ---------------------------------------------------------------------------
// Scratch (allocation banned -> __device__ globals)
// ---------------------------------------------------------------------------
__device__ float g_k[(size_t)M_ROWS * N_STATE];
__device__ float g_v[(size_t)M_ROWS * N_STATE];
__device__ float g_q[(size_t)M_ROWS * N_STATE];
__device__ float g_rnorm[M_ROWS];

__device__ __align__(16) __half g_xh[(size_t)M_ROWS * DIM_K];
__device__ __align__(16) __half g_wh[(size_t)3 * N_STATE * DIM_K];

// ---------------------------------------------------------------------------
// PTX helpers (compute_80-level)
// ---------------------------------------------------------------------------
__device__ __forceinline__ uint32_t smem_u32(const void* p) {
    uint32_t a;
    asm("{ .reg .u64 t; cvta.to.shared.u64 t, %1; cvt.u32.u64 %0, t; }"
        : "=r"(a) : "l"(p));
    return a;
}

__device__ __forceinline__ void cp_async16(uint32_t dst, const void* src) {
    asm volatile("cp.async.cg.shared.global [%0], [%1], 16;" :: "r"(dst), "l"(src));
}

__device__ __forceinline__ void ldsm4(uint32_t* r, uint32_t addr) {
    asm volatile("ldmatrix.sync.aligned.m8n8.x4.shared.b16 {%0,%1,%2,%3}, [%4];"
                 : "=r"(r[0]), "=r"(r[1]), "=r"(r[2]), "=r"(r[3]) : "r"(addr));
}

__device__ __forceinline__ void mma_f16(float* c, const uint32_t* a,
                                        uint32_t b0, uint32_t b1) {
    asm volatile(
        "mma.sync.aligned.m16n8k16.row.col.f32.f16.f16.f32 "
        "{%0,%1,%2,%3}, {%4,%5,%6,%7}, {%8,%9}, {%0,%1,%2,%3};"
        : "+f"(c[0]), "+f"(c[1]), "+f"(c[2]), "+f"(c[3])
        : "r"(a[0]), "r"(a[1]), "r"(a[2]), "r"(a[3]), "r"(b0), "r"(b1));
}

// ---------------------------------------------------------------------------
// ncu steering: two no-op launches so launch #6 = GEMM (observed offset 2)
// ---------------------------------------------------------------------------
__global__ void noop_kernel() {}

// ---------------------------------------------------------------------------
// fp32 -> fp16 convert, ALL tensors in one launch.
// Linear float4 index space: [0, n4x) -> x ; then 3 weight blocks of n4w each.
// ---------------------------------------------------------------------------
__global__ __launch_bounds__(256) void convert_kernel(
    const float* __restrict__ x,  const float* __restrict__ Wk,
    const float* __restrict__ Wv, const float* __restrict__ Wq)
{
    const int n4x = (M_ROWS * DIM_K) / 4;
    const int n4w = (N_STATE * DIM_K) / 4;
    const int i = blockIdx.x * 256 + threadIdx.x;

    const float* src;
    __half* h;
    int j;
    if (i < n4x) {
        src = x; h = g_xh; j = i;
    } else {
        const int w = (i - n4x) / n4w;           // 0..2
        j = (i - n4x) - w * n4w;
        src = (w == 0) ? Wk : ((w == 1) ? Wv : Wq);
        h = g_wh + (size_t)w * N_STATE * DIM_K;
    }

    const float4 v = ((const float4*)src)[j];
    __half2* hp = (__half2*)h;
    hp[2 * j]     = __floats2half2_rn(v.x, v.y);
    hp[2 * j + 1] = __floats2half2_rn(v.z, v.w);
}

// ---------------------------------------------------------------------------
// cp.async one BK=32 chunk of A and B tiles into a stage.
// Each thread: row r = tid/2, chunk c = (tid&1)*2 -> 4 cp.async of 16B.
// ---------------------------------------------------------------------------
__device__ __forceinline__ void issue_loads(
    uint32_t stage, int kt, int m0, int n0, int tid,
    const __half* __restrict__ wh)
{
    const int kc = kt * BK;
    const int r = tid >> 1;
    const int c = (tid & 1) * 2;               // 16B chunk index (0 or 2)
    const size_t ga = (size_t)(m0 + r) * DIM_K + kc + c * 8;
    const size_t gb = (size_t)(n0 + r) * DIM_K + kc + c * 8;
    const uint32_t so = (uint32_t)(r * LDS_B + c * 16);

    cp_async16(stage + OFF_A + so,      g_xh + ga);
    cp_async16(stage + OFF_A + so + 16, g_xh + ga + 8);
    cp_async16(stage + OFF_B + so,      wh + gb);
    cp_async16(stage + OFF_B + so + 16, wh + gb + 8);
}

// ---------------------------------------------------------------------------
// GEMM: C[m,n] = sum_d x[m,d] * W[n,d], single-pass fp16 via mma.sync.
// grid = (N/BN=8, M/BM=256, 3); 256 threads; warp tile 64x32; 2 CTAs/SM.
// ---------------------------------------------------------------------------
__global__ __launch_bounds__(256, 2) void gemm_mma_kernel()
{
    extern __shared__ __align__(16) char smem[];
    const int tid  = threadIdx.x;
    const int lane = tid & 31;
    const int wid  = tid >> 5;
    const int n0 = blockIdx.x * BN;
    const int m0 = blockIdx.y * BM;
    const int z  = blockIdx.z;

    const __half* wh = g_wh + (size_t)z * N_STATE * DIM_K;
    float* C = (z == 0) ? g_k : ((z == 1) ? g_v : g_q);

    const uint32_t sb = smem_u32(smem);

    // Warp tile origin within the CTA tile
    const int wm = (wid & 1) * 64;
    const int wn = (wid >> 1) * 32;

    // ldmatrix lane addressing: 16 rows x (two 8-col halves)
    const int lrow = (lane & 7) + (((lane >> 3) & 1) << 3);  // 0..15
    const int lkB  = (lane >> 4) * 16;                       // byte offset 0 or 16

    float acc[4][4][4];
    #pragma unroll
    for (int i = 0; i < 4; ++i)
        #pragma unroll
        for (int j = 0; j < 4; ++j)
            #pragma unroll
            for (int e = 0; e < 4; ++e) acc[i][j][e] = 0.0f;

    // Prologue: fill stages 0..2
    issue_loads(sb,                   0, m0, n0, tid, wh);
    asm volatile("cp.async.commit_group;" ::: "memory");
    issue_loads(sb + STAGE_BYTES,     1, m0, n0, tid, wh);
    asm volatile("cp.async.commit_group;" ::: "memory");
    issue_loads(sb + 2 * STAGE_BYTES, 2, m0, n0, tid, wh);
    asm volatile("cp.async.commit_group;" ::: "memory");

    for (int kt = 0; kt < NKT; ++kt) {
        if (kt < NKT - 2)      asm volatile("cp.async.wait_group 2;" ::: "memory");
        else if (kt < NKT - 1) asm volatile("cp.async.wait_group 1;" ::: "memory");
        else                   asm volatile("cp.async.wait_group 0;" ::: "memory");
        __syncthreads();

        // Refill the stage consumed at iteration kt-1 with chunk kt+3
        if (kt + 3 < NKT) {
            const uint32_t st = sb + (uint32_t)((kt + 3) % N_STAGE) * STAGE_BYTES;
            issue_loads(st, kt + 3, m0, n0, tid, wh);
            asm volatile("cp.async.commit_group;" ::: "memory");
        }

        const uint32_t stage = sb + (uint32_t)(kt % N_STAGE) * STAGE_BYTES;

        #pragma unroll
        for (int kk = 0; kk < 2; ++kk) {       // two k16 halves of BK=32
            const uint32_t kb = (uint32_t)(kk * 32 + lkB);  // byte offset in row

            uint32_t af[4][4];
            #pragma unroll
            for (int mi = 0; mi < 4; ++mi) {
                const uint32_t ra = (uint32_t)((wm + mi * 16 + lrow) * LDS_B) + kb;
                ldsm4(af[mi], stage + OFF_A + ra);
            }
            uint32_t bf[2][4];
            #pragma unroll
            for (int nj = 0; nj < 2; ++nj) {
                const uint32_t rb = (uint32_t)((wn + nj * 16 + lrow) * LDS_B) + kb;
                ldsm4(bf[nj], stage + OFF_B + rb);
            }

            #pragma unroll
            for (int mi = 0; mi < 4; ++mi)
                #pragma unroll
                for (int ni = 0; ni < 4; ++ni) {
                    const int nj = ni >> 1, p = ni & 1;
                    mma_f16(acc[mi][ni], af[mi], bf[nj][p], bf[nj][p + 2]);
                }
        }
        __syncthreads();
    }

    // Epilogue: fragment rows lane/4 and lane/4+8, cols (lane%4)*2
    const int er = lane >> 2;
    const int ec = (lane & 3) * 2;
    #pragma unroll
    for (int mi = 0; mi < 4; ++mi) {
        #pragma unroll
        for (int ni = 0; ni < 4; ++ni) {
            const size_t row = (size_t)(m0 + wm + mi * 16 + er);
            const size_t col = (size_t)(n0 + wn + ni * 8 + ec);
            *(float2*)(C + row * N_STATE + col) =
                make_float2(acc[mi][ni][0], acc[mi][ni][1]);
            *(float2*)(C + (row + 8) * N_STATE + col) =
                make_float2(acc[mi][ni][2], acc[mi][ni][3]);
        }
    }
}

// ---------------------------------------------------------------------------
// Row norms of k: one warp per row; stores 1/(||k||+eps).
// ---------------------------------------------------------------------------
__global__ __launch_bounds__(256) void rnorm_kernel()
{
    const int warp = threadIdx.x >> 5;
    const int lane = threadIdx.x & 31;
    const int row = blockIdx.x * 8 + warp;

    const float4* kp = (const float4*)(g_k + (size_t)row * N_STATE);
    float ss = 0.0f;
    #pragma unroll
    for (int j = 0; j < 8; ++j) {
        float4 v = kp[lane + j * 32];
        ss = fmaf(v.x, v.x, ss);
        ss = fmaf(v.y, v.y, ss);
        ss = fmaf(v.z, v.z, ss);
        ss = fmaf(v.w, v.w, ss);
    }
    #pragma unroll
    for (int o = 16; o > 0; o >>= 1)
        ss += __shfl_xor_sync(0xFFFFFFFFu, ss, o);

    if (lane == 0)
        g_rnorm[row] = 1.0f / (sqrtf(ss) + EPSF);
}

// ---------------------------------------------------------------------------
// Sequential scan: one thread per (b, n). rnorm cached in smem (one b per CTA).
// ---------------------------------------------------------------------------
__global__ __launch_bounds__(128) void scan_kernel(float* __restrict__ out,
                                                   float* __restrict__ s_final)
{
    __shared__ float srn[T_STEPS];
    const int s = blockIdx.x * 128 + threadIdx.x;    // 0..16383
    const int b = s >> 10;                           // whole CTA shares one b

    for (int t = threadIdx.x; t < T_STEPS; t += 128)
        srn[t] = g_rnorm[t * B_SZ + b];
    __syncthreads();

    float S = 0.0f;

    #pragma unroll 8
    for (int t = 0; t < T_STEPS; ++t) {
        const int idx = t * STATE_N + s;
        const float kraw = __ldcs(g_k + idx);
        const float v    = __ldcs(g_v + idx);
        const float q    = __ldcs(g_q + idx);
        const float rn   = srn[t];

        const float kn = kraw * rn;
        S = tanhf(fmaf(S, 1.0f - kn * kn, v * kn));
        const float Sq = S * q;
        const float o = (Sq * Sq) / (1.0f + __expf(-Sq));
        __stcs(out + idx, o);
    }

    if (s_final)
        s_final[s] = S;
}

// ---------------------------------------------------------------------------
// Launch
// ---------------------------------------------------------------------------
extern "C" void kernel_launch(void* const* d_in, const int* in_sizes, int n_in,
                              void* d_out, int out_size)
{
    const float* x  = (const float*)d_in[0];
    const float* Wk = (const float*)d_in[1];
    const float* Wv = (const float*)d_in[2];
    const float* Wq = (const float*)d_in[3];
    float* out = (float*)d_out;

    // ncu steering pads (launch #6 should land on the GEMM)
    noop_kernel<<<1, 32>>>();
    noop_kernel<<<1, 32>>>();

    // fp32 -> fp16 converts (single launch)
    const int n4tot = (M_ROWS * DIM_K) / 4 + 3 * ((N_STATE * DIM_K) / 4);
    convert_kernel<<<(n4tot + 255) / 256, 256>>>(x, Wk, Wv, Wq);

    // Tensor-core GEMM for k, v, q
    cudaFuncSetAttribute(gemm_mma_kernel,
                         cudaFuncAttributeMaxDynamicSharedMemorySize, SMEM_TOTAL);
    dim3 ggrid(N_STATE / BN, M_ROWS / BM, 3);
    gemm_mma_kernel<<<ggrid, 256, SMEM_TOTAL>>>();

    // Reciprocal row norms of k
    rnorm_kernel<<<M_ROWS / 8, 256>>>();

    // Scan over time
    float* s_final = nullptr;
    if (out_size >= M_ROWS * N_STATE + STATE_N)
        s_final = out + (size_t)M_ROWS * N_STATE;
    scan_kernel<<<STATE_N / 128, 128>>>(out, s_final);
}

// round 8
// speedup vs baseline: 4.4331x; 1.5850x over previous
#include <cuda_runtime.h>
#include <cuda_fp16.h>
#include <math.h>
#include <stdint.h>

// Problem constants (E74DiagonalCell)
#define T_STEPS 2048
#define B_SZ    16
#define DIM_K   1024
#define N_STATE 1024
#define M_ROWS  (T_STEPS * B_SZ)          // 32768
#define STATE_N (B_SZ * N_STATE)          // 16384
#define EPSF    1e-6f

// GEMM tiling (fp16 single-pass mma.sync; tcgen05 unavailable at compute_100)
#define BM 128
#define BN 128
#define BK 32
#define NKT (DIM_K / BK)                   // 32
#define LDS_B 80                           // padded row stride bytes (64B data + 16 pad)
#define TILE_BYTES (BM * LDS_B)            // 10240
#define OFF_A 0
#define OFF_B TILE_BYTES
#define STAGE_BYTES (2 * TILE_BYTES)       // 20480
#define N_STAGE 4
#define SMEM_TOTAL (N_STAGE * STAGE_BYTES) // 81920 -> 2 CTAs/SM

// ---------------------------------------------------------------------------
// Scratch (allocation banned -> __device__ globals)
// ---------------------------------------------------------------------------
__device__ float g_k[(size_t)M_ROWS * N_STATE];
__device__ float g_v[(size_t)M_ROWS * N_STATE];
__device__ float g_q[(size_t)M_ROWS * N_STATE];
__device__ float g_rnorm[M_ROWS];

__device__ __align__(16) __half g_xh[(size_t)M_ROWS * DIM_K];
__device__ __align__(16) __half g_wh[(size_t)3 * N_STATE * DIM_K];

// ---------------------------------------------------------------------------
// PTX helpers (compute_80-level)
// ---------------------------------------------------------------------------
__device__ __forceinline__ uint32_t smem_u32(const void* p) {
    uint32_t a;
    asm("{ .reg .u64 t; cvta.to.shared.u64 t, %1; cvt.u32.u64 %0, t; }"
        : "=r"(a) : "l"(p));
    return a;
}

__device__ __forceinline__ void cp_async16(uint32_t dst, const void* src) {
    asm volatile("cp.async.cg.shared.global [%0], [%1], 16;" :: "r"(dst), "l"(src));
}

__device__ __forceinline__ void ldsm4(uint32_t* r, uint32_t addr) {
    asm volatile("ldmatrix.sync.aligned.m8n8.x4.shared.b16 {%0,%1,%2,%3}, [%4];"
                 : "=r"(r[0]), "=r"(r[1]), "=r"(r[2]), "=r"(r[3]) : "r"(addr));
}

__device__ __forceinline__ void mma_f16(float* c, const uint32_t* a,
                                        uint32_t b0, uint32_t b1) {
    asm volatile(
        "mma.sync.aligned.m16n8k16.row.col.f32.f16.f16.f32 "
        "{%0,%1,%2,%3}, {%4,%5,%6,%7}, {%8,%9}, {%0,%1,%2,%3};"
        : "+f"(c[0]), "+f"(c[1]), "+f"(c[2]), "+f"(c[3])
        : "r"(a[0]), "r"(a[1]), "r"(a[2]), "r"(a[3]), "r"(b0), "r"(b1));
}

// Fast tanh / sigmoid (MUFU.EX2-based; rel err ~1e-7, vs 1e-3 budget)
__device__ __forceinline__ float tanh_fast(float x) {
    const float e = __expf(2.0f * x);
    return 1.0f - __fdividef(2.0f, e + 1.0f);
}

// ---------------------------------------------------------------------------
// fp32 -> fp16 convert, ALL tensors in one launch.
// ---------------------------------------------------------------------------
__global__ __launch_bounds__(256) void convert_kernel(
    const float* __restrict__ x,  const float* __restrict__ Wk,
    const float* __restrict__ Wv, const float* __restrict__ Wq)
{
    const int n4x = (M_ROWS * DIM_K) / 4;
    const int n4w = (N_STATE * DIM_K) / 4;
    const int i = blockIdx.x * 256 + threadIdx.x;

    const float* src;
    __half* h;
    int j;
    if (i < n4x) {
        src = x; h = g_xh; j = i;
    } else {
        const int w = (i - n4x) / n4w;           // 0..2
        j = (i - n4x) - w * n4w;
        src = (w == 0) ? Wk : ((w == 1) ? Wv : Wq);
        h = g_wh + (size_t)w * N_STATE * DIM_K;
    }

    const float4 v = ((const float4*)src)[j];
    __half2* hp = (__half2*)h;
    hp[2 * j]     = __floats2half2_rn(v.x, v.y);
    hp[2 * j + 1] = __floats2half2_rn(v.z, v.w);
}

// ---------------------------------------------------------------------------
// cp.async one BK=32 chunk of A and B tiles into a stage.
// ---------------------------------------------------------------------------
__device__ __forceinline__ void issue_loads(
    uint32_t stage, int kt, int m0, int n0, int tid,
    const __half* __restrict__ wh)
{
    const int kc = kt * BK;
    const int r = tid >> 1;
    const int c = (tid & 1) * 2;               // 16B chunk index (0 or 2)
    const size_t ga = (size_t)(m0 + r) * DIM_K + kc + c * 8;
    const size_t gb = (size_t)(n0 + r) * DIM_K + kc + c * 8;
    const uint32_t so = (uint32_t)(r * LDS_B + c * 16);

    cp_async16(stage + OFF_A + so,      g_xh + ga);
    cp_async16(stage + OFF_A + so + 16, g_xh + ga + 8);
    cp_async16(stage + OFF_B + so,      wh + gb);
    cp_async16(stage + OFF_B + so + 16, wh + gb + 8);
}

// ---------------------------------------------------------------------------
// GEMM: C[m,n] = sum_d x[m,d] * W[n,d], single-pass fp16 via mma.sync.
// grid = (N/BN=8, M/BM=256, 3); 256 threads; warp tile 64x32; 2 CTAs/SM.
// ---------------------------------------------------------------------------
__global__ __launch_bounds__(256, 2) void gemm_mma_kernel()
{
    extern __shared__ __align__(16) char smem[];
    const int tid  = threadIdx.x;
    const int lane = tid & 31;
    const int wid  = tid >> 5;
    const int n0 = blockIdx.x * BN;
    const int m0 = blockIdx.y * BM;
    const int z  = blockIdx.z;

    const __half* wh = g_wh + (size_t)z * N_STATE * DIM_K;
    float* C = (z == 0) ? g_k : ((z == 1) ? g_v : g_q);

    const uint32_t sb = smem_u32(smem);

    const int wm = (wid & 1) * 64;
    const int wn = (wid >> 1) * 32;

    const int lrow = (lane & 7) + (((lane >> 3) & 1) << 3);  // 0..15
    const int lkB  = (lane >> 4) * 16;                       // byte offset 0 or 16

    float acc[4][4][4];
    #pragma unroll
    for (int i = 0; i < 4; ++i)
        #pragma unroll
        for (int j = 0; j < 4; ++j)
            #pragma unroll
            for (int e = 0; e < 4; ++e) acc[i][j][e] = 0.0f;

    // Prologue: fill stages 0..2
    issue_loads(sb,                   0, m0, n0, tid, wh);
    asm volatile("cp.async.commit_group;" ::: "memory");
    issue_loads(sb + STAGE_BYTES,     1, m0, n0, tid, wh);
    asm volatile("cp.async.commit_group;" ::: "memory");
    issue_loads(sb + 2 * STAGE_BYTES, 2, m0, n0, tid, wh);
    asm volatile("cp.async.commit_group;" ::: "memory");

    for (int kt = 0; kt < NKT; ++kt) {
        if (kt < NKT - 2)      asm volatile("cp.async.wait_group 2;" ::: "memory");
        else if (kt < NKT - 1) asm volatile("cp.async.wait_group 1;" ::: "memory");
        else                   asm volatile("cp.async.wait_group 0;" ::: "memory");
        __syncthreads();
        // NOTE: single barrier per kt. Refill below targets stage (kt+3)%4,
        // whose readers finished during iteration kt-1, i.e. before this
        // barrier -> no end-of-loop barrier needed.

        if (kt + 3 < NKT) {
            const uint32_t st = sb + (uint32_t)((kt + 3) % N_STAGE) * STAGE_BYTES;
            issue_loads(st, kt + 3, m0, n0, tid, wh);
            asm volatile("cp.async.commit_group;" ::: "memory");
        }

        const uint32_t stage = sb + (uint32_t)(kt % N_STAGE) * STAGE_BYTES;

        #pragma unroll
        for (int kk = 0; kk < 2; ++kk) {       // two k16 halves of BK=32
            const uint32_t kb = (uint32_t)(kk * 32 + lkB);

            uint32_t af[4][4];
            #pragma unroll
            for (int mi = 0; mi < 4; ++mi) {
                const uint32_t ra = (uint32_t)((wm + mi * 16 + lrow) * LDS_B) + kb;
                ldsm4(af[mi], stage + OFF_A + ra);
            }
            uint32_t bf[2][4];
            #pragma unroll
            for (int nj = 0; nj < 2; ++nj) {
                const uint32_t rb = (uint32_t)((wn + nj * 16 + lrow) * LDS_B) + kb;
                ldsm4(bf[nj], stage + OFF_B + rb);
            }

            #pragma unroll
            for (int mi = 0; mi < 4; ++mi)
                #pragma unroll
                for (int ni = 0; ni < 4; ++ni) {
                    const int nj = ni >> 1, p = ni & 1;
                    mma_f16(acc[mi][ni], af[mi], bf[nj][p], bf[nj][p + 2]);
                }
        }
    }
    __syncthreads();

    // Epilogue
    const int er = lane >> 2;
    const int ec = (lane & 3) * 2;
    #pragma unroll
    for (int mi = 0; mi < 4; ++mi) {
        #pragma unroll
        for (int ni = 0; ni < 4; ++ni) {
            const size_t row = (size_t)(m0 + wm + mi * 16 + er);
            const size_t col = (size_t)(n0 + wn + ni * 8 + ec);
            *(float2*)(C + row * N_STATE + col) =
                make_float2(acc[mi][ni][0], acc[mi][ni][1]);
            *(float2*)(C + (row + 8) * N_STATE + col) =
                make_float2(acc[mi][ni][2], acc[mi][ni][3]);
        }
    }
}

// ---------------------------------------------------------------------------
// Row norms of k: one warp per row; stores 1/(||k||+eps).
// ---------------------------------------------------------------------------
__global__ __launch_bounds__(256) void rnorm_kernel()
{
    const int warp = threadIdx.x >> 5;
    const int lane = threadIdx.x & 31;
    const int row = blockIdx.x * 8 + warp;

    const float4* kp = (const float4*)(g_k + (size_t)row * N_STATE);
    float ss = 0.0f;
    #pragma unroll
    for (int j = 0; j < 8; ++j) {
        float4 v = kp[lane + j * 32];
        ss = fmaf(v.x, v.x, ss);
        ss = fmaf(v.y, v.y, ss);
        ss = fmaf(v.z, v.z, ss);
        ss = fmaf(v.w, v.w, ss);
    }
    #pragma unroll
    for (int o = 16; o > 0; o >>= 1)
        ss += __shfl_xor_sync(0xFFFFFFFFu, ss, o);

    if (lane == 0)
        g_rnorm[row] = 1.0f / (sqrtf(ss) + EPSF);
}

// ---------------------------------------------------------------------------
// Sequential scan: one thread per (b, n) state.
// Software-pipelined: double-buffered register blocks of D=8 timesteps;
// the next block's 24 loads are issued before computing the current block.
// ---------------------------------------------------------------------------
#define SCAN_D 8

__global__ __launch_bounds__(128) void scan_kernel(float* __restrict__ out,
                                                   float* __restrict__ s_final)
{
    __shared__ float srn[T_STEPS];
    const int s = blockIdx.x * 128 + threadIdx.x;    // 0..16383
    const int b = s >> 10;                           // whole CTA shares one b

    for (int t = threadIdx.x; t < T_STEPS; t += 128)
        srn[t] = g_rnorm[t * B_SZ + b];
    __syncthreads();

    const float* __restrict__ kp = g_k + s;
    const float* __restrict__ vp = g_v + s;
    const float* __restrict__ qp = g_q + s;
    float* __restrict__ op = out + s;

    float kb[2][SCAN_D], vb[2][SCAN_D], qb[2][SCAN_D];

    // Preload block 0
    #pragma unroll
    for (int d = 0; d < SCAN_D; ++d) {
        const size_t o = (size_t)d * STATE_N;
        kb[0][d] = __ldcs(kp + o);
        vb[0][d] = __ldcs(vp + o);
        qb[0][d] = __ldcs(qp + o);
    }

    float S = 0.0f;
    int cur = 0;

    for (int t0 = 0; t0 < T_STEPS; t0 += SCAN_D) {
        const int nxt = cur ^ 1;

        // Issue next block's loads (independent of S) before computing
        if (t0 + SCAN_D < T_STEPS) {
            #pragma unroll
            for (int d = 0; d < SCAN_D; ++d) {
                const size_t o = (size_t)(t0 + SCAN_D + d) * STATE_N;
                kb[nxt][d] = __ldcs(kp + o);
                vb[nxt][d] = __ldcs(vp + o);
                qb[nxt][d] = __ldcs(qp + o);
            }
        }

        #pragma unroll
        for (int d = 0; d < SCAN_D; ++d) {
            const float rn = srn[t0 + d];
            const float kn = kb[cur][d] * rn;
            S = tanh_fast(fmaf(S, 1.0f - kn * kn, vb[cur][d] * kn));
            const float Sq = S * qb[cur][d];
            const float o = Sq * Sq * __fdividef(1.0f, 1.0f + __expf(-Sq));
            __stcs(op + (size_t)(t0 + d) * STATE_N, o);
        }

        cur = nxt;
    }

    if (s_final)
        s_final[s] = S;
}

// ---------------------------------------------------------------------------
// Launch.  Order: convert, gemm, rnorm, scan -> with the 2 hidden harness
// launches, ncu -s 5 -c 1 captures the SCAN next round.
// ---------------------------------------------------------------------------
extern "C" void kernel_launch(void* const* d_in, const int* in_sizes, int n_in,
                              void* d_out, int out_size)
{
    const float* x  = (const float*)d_in[0];
    const float* Wk = (const float*)d_in[1];
    const float* Wv = (const float*)d_in[2];
    const float* Wq = (const float*)d_in[3];
    float* out = (float*)d_out;

    // fp32 -> fp16 converts (single launch)
    const int n4tot = (M_ROWS * DIM_K) / 4 + 3 * ((N_STATE * DIM_K) / 4);
    convert_kernel<<<(n4tot + 255) / 256, 256>>>(x, Wk, Wv, Wq);

    // Tensor-core GEMM for k, v, q
    cudaFuncSetAttribute(gemm_mma_kernel,
                         cudaFuncAttributeMaxDynamicSharedMemorySize, SMEM_TOTAL);
    dim3 ggrid(N_STATE / BN, M_ROWS / BM, 3);
    gemm_mma_kernel<<<ggrid, 256, SMEM_TOTAL>>>();

    // Reciprocal row norms of k
    rnorm_kernel<<<M_ROWS / 8, 256>>>();

    // Scan over time
    float* s_final = nullptr;
    if (out_size >= M_ROWS * N_STATE + STATE_N)
        s_final = out + (size_t)M_ROWS * N_STATE;
    scan_kernel<<<STATE_N / 128, 128>>>(out, s_final);
}

// round 9
// speedup vs baseline: 5.6693x; 1.2789x over previous
#include <cuda_runtime.h>
#include <cuda_fp16.h>
#include <math.h>
#include <stdint.h>

// Problem constants (E74DiagonalCell)
#define T_STEPS 2048
#define B_SZ    16
#define DIM_K   1024
#define N_STATE 1024
#define M_ROWS  (T_STEPS * B_SZ)          // 32768
#define STATE_N (B_SZ * N_STATE)          // 16384
#define EPSF    1e-6f

// GEMM tiling (fp16 single-pass mma.sync; tcgen05 unavailable at compute_100)
#define BM 128
#define BN 128
#define BK 32
#define NKT (DIM_K / BK)                   // 32
#define LDS_B 80                           // padded row stride bytes (64B data + 16 pad)
#define TILE_BYTES (BM * LDS_B)            // 10240
#define OFF_A 0
#define OFF_B TILE_BYTES
#define STAGE_BYTES (2 * TILE_BYTES)       // 20480
#define N_STAGE 4
#define SMEM_TOTAL (N_STAGE * STAGE_BYTES) // 81920 -> 2 CTAs/SM

// ---------------------------------------------------------------------------
// Scratch (allocation banned -> __device__ globals)
// ---------------------------------------------------------------------------
__device__ float g_k[(size_t)M_ROWS * N_STATE];
__device__ float g_v[(size_t)M_ROWS * N_STATE];
__device__ float g_q[(size_t)M_ROWS * N_STATE];
__device__ float g_rnorm[M_ROWS];          // TRANSPOSED: [b][t]

__device__ __align__(16) __half g_xh[(size_t)M_ROWS * DIM_K];
__device__ __align__(16) __half g_wh[(size_t)3 * N_STATE * DIM_K];

// ---------------------------------------------------------------------------
// PTX helpers (compute_80-level)
// ---------------------------------------------------------------------------
__device__ __forceinline__ uint32_t smem_u32(const void* p) {
    uint32_t a;
    asm("{ .reg .u64 t; cvta.to.shared.u64 t, %1; cvt.u32.u64 %0, t; }"
        : "=r"(a) : "l"(p));
    return a;
}

__device__ __forceinline__ void cp_async16(uint32_t dst, const void* src) {
    asm volatile("cp.async.cg.shared.global [%0], [%1], 16;" :: "r"(dst), "l"(src));
}

__device__ __forceinline__ void ldsm4(uint32_t* r, uint32_t addr) {
    asm volatile("ldmatrix.sync.aligned.m8n8.x4.shared.b16 {%0,%1,%2,%3}, [%4];"
                 : "=r"(r[0]), "=r"(r[1]), "=r"(r[2]), "=r"(r[3]) : "r"(addr));
}

__device__ __forceinline__ void mma_f16(float* c, const uint32_t* a,
                                        uint32_t b0, uint32_t b1) {
    asm volatile(
        "mma.sync.aligned.m16n8k16.row.col.f32.f16.f16.f32 "
        "{%0,%1,%2,%3}, {%4,%5,%6,%7}, {%8,%9}, {%0,%1,%2,%3};"
        : "+f"(c[0]), "+f"(c[1]), "+f"(c[2]), "+f"(c[3])
        : "r"(a[0]), "r"(a[1]), "r"(a[2]), "r"(a[3]), "r"(b0), "r"(b1));
}

// Raw MUFU ops (guaranteed single-instruction approx paths)
__device__ __forceinline__ float ex2f(float x) {
    float y; asm("ex2.approx.ftz.f32 %0, %1;" : "=f"(y) : "f"(x)); return y;
}
__device__ __forceinline__ float rcpf(float x) {
    float y; asm("rcp.approx.ftz.f32 %0, %1;" : "=f"(y) : "f"(x)); return y;
}

#define LOG2E_F   1.4426950408889634f
#define C2LOG2E_F 2.8853900817779268f     // 2*log2(e)

// ---------------------------------------------------------------------------
// fp32 -> fp16 convert, ALL tensors in one launch.
// ---------------------------------------------------------------------------
__global__ __launch_bounds__(256) void convert_kernel(
    const float* __restrict__ x,  const float* __restrict__ Wk,
    const float* __restrict__ Wv, const float* __restrict__ Wq)
{
    const int n4x = (M_ROWS * DIM_K) / 4;
    const int n4w = (N_STATE * DIM_K) / 4;
    const int i = blockIdx.x * 256 + threadIdx.x;

    const float* src;
    __half* h;
    int j;
    if (i < n4x) {
        src = x; h = g_xh; j = i;
    } else {
        const int w = (i - n4x) / n4w;           // 0..2
        j = (i - n4x) - w * n4w;
        src = (w == 0) ? Wk : ((w == 1) ? Wv : Wq);
        h = g_wh + (size_t)w * N_STATE * DIM_K;
    }

    const float4 v = ((const float4*)src)[j];
    __half2* hp = (__half2*)h;
    hp[2 * j]     = __floats2half2_rn(v.x, v.y);
    hp[2 * j + 1] = __floats2half2_rn(v.z, v.w);
}

// ---------------------------------------------------------------------------
// cp.async one BK=32 chunk of A and B tiles into a stage.
// ---------------------------------------------------------------------------
__device__ __forceinline__ void issue_loads(
    uint32_t stage, int kt, int m0, int n0, int tid,
    const __half* __restrict__ wh)
{
    const int kc = kt * BK;
    const int r = tid >> 1;
    const int c = (tid & 1) * 2;               // 16B chunk index (0 or 2)
    const size_t ga = (size_t)(m0 + r) * DIM_K + kc + c * 8;
    const size_t gb = (size_t)(n0 + r) * DIM_K + kc + c * 8;
    const uint32_t so = (uint32_t)(r * LDS_B + c * 16);

    cp_async16(stage + OFF_A + so,      g_xh + ga);
    cp_async16(stage + OFF_A + so + 16, g_xh + ga + 8);
    cp_async16(stage + OFF_B + so,      wh + gb);
    cp_async16(stage + OFF_B + so + 16, wh + gb + 8);
}

// ---------------------------------------------------------------------------
// GEMM: C[m,n] = sum_d x[m,d] * W[n,d], single-pass fp16 via mma.sync.
// grid = (N/BN=8, M/BM=256, 3); 256 threads; warp tile 64x32; 2 CTAs/SM.
// ---------------------------------------------------------------------------
__global__ __launch_bounds__(256, 2) void gemm_mma_kernel()
{
    extern __shared__ __align__(16) char smem[];
    const int tid  = threadIdx.x;
    const int lane = tid & 31;
    const int wid  = tid >> 5;
    const int n0 = blockIdx.x * BN;
    const int m0 = blockIdx.y * BM;
    const int z  = blockIdx.z;

    const __half* wh = g_wh + (size_t)z * N_STATE * DIM_K;
    float* C = (z == 0) ? g_k : ((z == 1) ? g_v : g_q);

    const uint32_t sb = smem_u32(smem);

    const int wm = (wid & 1) * 64;
    const int wn = (wid >> 1) * 32;

    const int lrow = (lane & 7) + (((lane >> 3) & 1) << 3);  // 0..15
    const int lkB  = (lane >> 4) * 16;                       // byte offset 0 or 16

    float acc[4][4][4];
    #pragma unroll
    for (int i = 0; i < 4; ++i)
        #pragma unroll
        for (int j = 0; j < 4; ++j)
            #pragma unroll
            for (int e = 0; e < 4; ++e) acc[i][j][e] = 0.0f;

    // Prologue: fill stages 0..2
    issue_loads(sb,                   0, m0, n0, tid, wh);
    asm volatile("cp.async.commit_group;" ::: "memory");
    issue_loads(sb + STAGE_BYTES,     1, m0, n0, tid, wh);
    asm volatile("cp.async.commit_group;" ::: "memory");
    issue_loads(sb + 2 * STAGE_BYTES, 2, m0, n0, tid, wh);
    asm volatile("cp.async.commit_group;" ::: "memory");

    for (int kt = 0; kt < NKT; ++kt) {
        if (kt < NKT - 2)      asm volatile("cp.async.wait_group 2;" ::: "memory");
        else if (kt < NKT - 1) asm volatile("cp.async.wait_group 1;" ::: "memory");
        else                   asm volatile("cp.async.wait_group 0;" ::: "memory");
        __syncthreads();

        if (kt + 3 < NKT) {
            const uint32_t st = sb + (uint32_t)((kt + 3) % N_STAGE) * STAGE_BYTES;
            issue_loads(st, kt + 3, m0, n0, tid, wh);
            asm volatile("cp.async.commit_group;" ::: "memory");
        }

        const uint32_t stage = sb + (uint32_t)(kt % N_STAGE) * STAGE_BYTES;

        #pragma unroll
        for (int kk = 0; kk < 2; ++kk) {       // two k16 halves of BK=32
            const uint32_t kb = (uint32_t)(kk * 32 + lkB);

            uint32_t af[4][4];
            #pragma unroll
            for (int mi = 0; mi < 4; ++mi) {
                const uint32_t ra = (uint32_t)((wm + mi * 16 + lrow) * LDS_B) + kb;
                ldsm4(af[mi], stage + OFF_A + ra);
            }
            uint32_t bf[2][4];
            #pragma unroll
            for (int nj = 0; nj < 2; ++nj) {
                const uint32_t rb = (uint32_t)((wn + nj * 16 + lrow) * LDS_B) + kb;
                ldsm4(bf[nj], stage + OFF_B + rb);
            }

            #pragma unroll
            for (int mi = 0; mi < 4; ++mi)
                #pragma unroll
                for (int ni = 0; ni < 4; ++ni) {
                    const int nj = ni >> 1, p = ni & 1;
                    mma_f16(acc[mi][ni], af[mi], bf[nj][p], bf[nj][p + 2]);
                }
        }
    }
    __syncthreads();

    // Epilogue
    const int er = lane >> 2;
    const int ec = (lane & 3) * 2;
    #pragma unroll
    for (int mi = 0; mi < 4; ++mi) {
        #pragma unroll
        for (int ni = 0; ni < 4; ++ni) {
            const size_t row = (size_t)(m0 + wm + mi * 16 + er);
            const size_t col = (size_t)(n0 + wn + ni * 8 + ec);
            *(float2*)(C + row * N_STATE + col) =
                make_float2(acc[mi][ni][0], acc[mi][ni][1]);
            *(float2*)(C + (row + 8) * N_STATE + col) =
                make_float2(acc[mi][ni][2], acc[mi][ni][3]);
        }
    }
}

// ---------------------------------------------------------------------------
// Row norms of k: one warp per row; stores 1/(||k||+eps) TRANSPOSED [b][t]
// so the scan's smem fill is coalesced.
// ---------------------------------------------------------------------------
__global__ __launch_bounds__(256) void rnorm_kernel()
{
    const int warp = threadIdx.x >> 5;
    const int lane = threadIdx.x & 31;
    const int row = blockIdx.x * 8 + warp;   // row = t*B_SZ + b

    const float4* kp = (const float4*)(g_k + (size_t)row * N_STATE);
    float ss = 0.0f;
    #pragma unroll
    for (int j = 0; j < 8; ++j) {
        float4 v = kp[lane + j * 32];
        ss = fmaf(v.x, v.x, ss);
        ss = fmaf(v.y, v.y, ss);
        ss = fmaf(v.z, v.z, ss);
        ss = fmaf(v.w, v.w, ss);
    }
    #pragma unroll
    for (int o = 16; o > 0; o >>= 1)
        ss += __shfl_xor_sync(0xFFFFFFFFu, ss, o);

    if (lane == 0) {
        const int t = row >> 4;              // row / B_SZ
        const int b = row & 15;              // row % B_SZ
        g_rnorm[b * T_STEPS + t] = 1.0f / (sqrtf(ss) + EPSF);
    }
}

// ---------------------------------------------------------------------------
// Sequential scan: one thread per (b, n) state.
// STATIC software pipeline: two explicit register buffer sets of D=16 steps;
// outer loop advances 2*D so buffer selection is compile-time (no dynamic
// register-array indexing -> no local spills).
// Recurrence chain per step: FMA -> EX2 -> ADD -> RCP -> FMA (~44 cyc).
//   S' = tanh(S*(1-kn^2) + v*kn) = 1 - 2/(exp2(S*c1 + c2) + 1)
//   c1 = 2*log2e*(1-kn^2), c2 = 2*log2e*v*kn   (off-chain precompute)
// ---------------------------------------------------------------------------
#define SCAN_D 16

#define SCAN_LOAD(KB, VB, QB, T0)                                        \
    _Pragma("unroll")                                                    \
    for (int d = 0; d < SCAN_D; ++d) {                                   \
        const size_t o = (size_t)((T0) + d) * STATE_N;                   \
        KB[d] = __ldcs(kp + o);                                          \
        VB[d] = __ldcs(vp + o);                                          \
        QB[d] = __ldcs(qp + o);                                          \
    }

#define SCAN_COMPUTE(KB, VB, QB, T0)                                     \
    _Pragma("unroll")                                                    \
    for (int d = 0; d < SCAN_D; ++d) {                                   \
        const float rn = srn[(T0) + d];                                  \
        const float kn = KB[d] * rn;                                     \
        const float c1 = C2LOG2E_F * fmaf(-kn, kn, 1.0f);                \
        const float c2 = C2LOG2E_F * (VB[d] * kn);                       \
        const float e  = ex2f(fmaf(S, c1, c2));                          \
        const float r  = rcpf(e + 1.0f);                                 \
        S = fmaf(-2.0f, r, 1.0f);                                        \
        const float Sq = S * QB[d];                                      \
        const float sg = rcpf(1.0f + ex2f(-LOG2E_F * Sq));               \
        __stcs(op + (size_t)((T0) + d) * STATE_N, Sq * Sq * sg);         \
    }

__global__ __launch_bounds__(128) void scan_kernel(float* __restrict__ out,
                                                   float* __restrict__ s_final)
{
    __shared__ float srn[T_STEPS];
    const int s = blockIdx.x * 128 + threadIdx.x;    // 0..16383
    const int b = s >> 10;                           // whole CTA shares one b

    // Coalesced: g_rnorm is [b][t]
    for (int t = threadIdx.x; t < T_STEPS; t += 128)
        srn[t] = g_rnorm[b * T_STEPS + t];
    __syncthreads();

    const float* __restrict__ kp = g_k + s;
    const float* __restrict__ vp = g_v + s;
    const float* __restrict__ qp = g_q + s;
    float* __restrict__ op = out + s;

    float ka[SCAN_D], va[SCAN_D], qa[SCAN_D];
    float kb[SCAN_D], vb[SCAN_D], qb[SCAN_D];

    SCAN_LOAD(ka, va, qa, 0)

    float S = 0.0f;

    for (int t0 = 0; t0 < T_STEPS; t0 += 2 * SCAN_D) {
        // Prefetch block B (t0+D) -- always in range since t0 <= T-2D
        SCAN_LOAD(kb, vb, qb, t0 + SCAN_D)
        // Compute block A while B's loads are in flight
        SCAN_COMPUTE(ka, va, qa, t0)
        // Prefetch next block A (t0+2D)
        if (t0 + 2 * SCAN_D < T_STEPS) {
            SCAN_LOAD(ka, va, qa, t0 + 2 * SCAN_D)
        }
        // Compute block B
        SCAN_COMPUTE(kb, vb, qb, t0 + SCAN_D)
    }

    if (s_final)
        s_final[s] = S;
}

// ---------------------------------------------------------------------------
// Launch
// ---------------------------------------------------------------------------
extern "C" void kernel_launch(void* const* d_in, const int* in_sizes, int n_in,
                              void* d_out, int out_size)
{
    const float* x  = (const float*)d_in[0];
    const float* Wk = (const float*)d_in[1];
    const float* Wv = (const float*)d_in[2];
    const float* Wq = (const float*)d_in[3];
    float* out = (float*)d_out;

    // fp32 -> fp16 converts (single launch)
    const int n4tot = (M_ROWS * DIM_K) / 4 + 3 * ((N_STATE * DIM_K) / 4);
    convert_kernel<<<(n4tot + 255) / 256, 256>>>(x, Wk, Wv, Wq);

    // Tensor-core GEMM for k, v, q
    cudaFuncSetAttribute(gemm_mma_kernel,
                         cudaFuncAttributeMaxDynamicSharedMemorySize, SMEM_TOTAL);
    dim3 ggrid(N_STATE / BN, M_ROWS / BM, 3);
    gemm_mma_kernel<<<ggrid, 256, SMEM_TOTAL>>>();

    // Reciprocal row norms of k (stored transposed [b][t])
    rnorm_kernel<<<M_ROWS / 8, 256>>>();

    // Scan over time
    float* s_final = nullptr;
    if (out_size >= M_ROWS * N_STATE + STATE_N)
        s_final = out + (size_t)M_ROWS * N_STATE;
    scan_kernel<<<STATE_N / 128, 128>>>(out, s_final);
}